// round 2
// baseline (speedup 1.0000x reference)
#include <cuda_runtime.h>
#include <cuda_bf16.h>

// Problem constants (fixed by setup_inputs)
#define N_NODES 50000
#define N_EDGES 1600000
#define N_EDGES_T (N_EDGES + N_NODES)   // with self loops = 1,650,000
#define F_IN 64
#define HC1 128          // H1*C1 = 4*32
#define C2 32
#define NG 512

// Scratch (device globals — no allocation allowed)
__device__ float g_h1[N_NODES * HC1];
__device__ float g_asrc1[N_NODES * 4];
__device__ float g_adst1[N_NODES * 4];
__device__ float g_denom1[N_NODES * 4];
__device__ float g_out1[N_NODES * HC1];
__device__ float g_h2[N_NODES * C2];
__device__ float g_asrc2[N_NODES];
__device__ float g_adst2[N_NODES];
__device__ float g_denom2[N_NODES];
__device__ float g_out2[N_NODES * C2];
__device__ float g_gsum[NG * C2];
__device__ float g_gcnt[NG];

// Decoded indices (int32, robust to harness delivering int32 or int64)
__device__ int g_src[N_EDGES];
__device__ int g_dst[N_EDGES];
__device__ int g_batch[N_NODES];
__device__ int g_ei_not64;
__device__ int g_b_not64;

__global__ void k_init() {
    int i = blockIdx.x * blockDim.x + threadIdx.x;
    int stride = gridDim.x * blockDim.x;
    for (int j = i; j < N_NODES * HC1; j += stride) g_out1[j] = 0.0f;
    for (int j = i; j < N_NODES * C2;  j += stride) g_out2[j] = 0.0f;
    for (int j = i; j < N_NODES * 4;   j += stride) g_denom1[j] = 0.0f;
    for (int j = i; j < N_NODES;       j += stride) g_denom2[j] = 0.0f;
    if (i < NG * C2) g_gsum[i] = 0.0f;
    if (i < NG)      g_gcnt[i] = 0.0f;
    if (i == 0) { g_ei_not64 = 0; g_b_not64 = 0; }
}

// Detect whether edge_index / batch buffers hold int64 or int32.
// We only read int64 words at indices < elems/2, which is in-bounds under
// EITHER interpretation. If the underlying data is int32, the int64 view packs
// two values: any nonzero high word -> value out of range -> flag.
__global__ void k_detect(const long long* __restrict__ ei,
                         const long long* __restrict__ batch) {
    int i = blockIdx.x * blockDim.x + threadIdx.x;
    int stride = gridDim.x * blockDim.x;
    for (int j = i; j < N_EDGES; j += stride) {        // 3.2M elems -> 1.6M safe i64 words
        long long v = ei[j];
        if (v < 0 || v >= N_NODES) { g_ei_not64 = 1; break; }
    }
    for (int j = i; j < N_NODES / 2; j += stride) {    // 50000 elems -> 25000 safe i64 words
        long long v = batch[j];
        if (v < 0 || v >= NG) { g_b_not64 = 1; break; }
    }
}

__global__ void k_decode(const void* __restrict__ ei, const void* __restrict__ batch) {
    int i = blockIdx.x * blockDim.x + threadIdx.x;
    int stride = gridDim.x * blockDim.x;
    bool e64 = (g_ei_not64 == 0);
    bool b64 = (g_b_not64 == 0);
    const long long* eL = (const long long*)ei;
    const int*       eI = (const int*)ei;
    const long long* bL = (const long long*)batch;
    const int*       bI = (const int*)batch;
    for (int j = i; j < N_EDGES; j += stride) {
        g_src[j] = e64 ? (int)eL[j]           : eI[j];
        g_dst[j] = e64 ? (int)eL[N_EDGES + j] : eI[N_EDGES + j];
    }
    for (int j = i; j < N_NODES; j += stride) {
        g_batch[j] = b64 ? (int)bL[j] : bI[j];
    }
}

// GEMM1: h1 = x @ W1  (50000x64 @ 64x128), fused per-head alpha epilogue.
// blockDim = 128 (1 thread per output column; warp w == head w).
// 16 rows per block; 50000 = 16 * 3125 exactly.
__global__ void k_gemm1(const float* __restrict__ x, const float* __restrict__ W1,
                        const float* __restrict__ a_src, const float* __restrict__ a_dst) {
    __shared__ float Ws[F_IN * HC1];   // 32 KB
    __shared__ float xs[F_IN];
    int t = threadIdx.x;
    for (int i = t; i < F_IN * HC1; i += 128) Ws[i] = W1[i];
    float av_s = a_src[t];
    float av_d = a_dst[t];
    int head = t >> 5;
    int base = blockIdx.x * 16;
    for (int r = 0; r < 16; ++r) {
        int row = base + r;
        __syncthreads();
        if (t < F_IN) xs[t] = x[row * F_IN + t];
        __syncthreads();
        float acc = 0.0f;
        #pragma unroll
        for (int k = 0; k < F_IN; ++k) acc += xs[k] * Ws[k * HC1 + t];
        g_h1[row * HC1 + t] = acc;
        float vs = acc * av_s, vd = acc * av_d;
        #pragma unroll
        for (int o = 16; o > 0; o >>= 1) {
            vs += __shfl_xor_sync(0xffffffffu, vs, o);
            vd += __shfl_xor_sync(0xffffffffu, vd, o);
        }
        if ((t & 31) == 0) {
            g_asrc1[row * 4 + head] = vs;
            g_adst1[row * 4 + head] = vd;
        }
    }
}

__device__ __forceinline__ float leaky(float v) {
    return v > 0.0f ? v : 0.2f * v;
}

// Layer-1 edge denominator: one thread per edge, 4 heads via float4.
__global__ void k_edge_den1() {
    int e = blockIdx.x * blockDim.x + threadIdx.x;
    if (e >= N_EDGES_T) return;
    int s, d;
    if (e < N_EDGES) { s = g_src[e]; d = g_dst[e]; }
    else             { s = e - N_EDGES; d = s; }
    float4 as = *(const float4*)&g_asrc1[s * 4];
    float4 ad = *(const float4*)&g_adst1[d * 4];
    float e0 = __expf(leaky(as.x + ad.x));
    float e1 = __expf(leaky(as.y + ad.y));
    float e2 = __expf(leaky(as.z + ad.z));
    float e3 = __expf(leaky(as.w + ad.w));
    atomicAdd(&g_denom1[d * 4 + 0], e0);
    atomicAdd(&g_denom1[d * 4 + 1], e1);
    atomicAdd(&g_denom1[d * 4 + 2], e2);
    atomicAdd(&g_denom1[d * 4 + 3], e3);
}

// Layer-1 aggregation: one warp per edge; lane c of head h handles channel h*32+c.
__global__ void k_edge_agg1() {
    long long gtid = (long long)blockIdx.x * blockDim.x + threadIdx.x;
    long long gw = gtid >> 5;
    int lane = threadIdx.x & 31;
    if (gw >= N_EDGES_T) return;
    int s, d;
    if (gw < N_EDGES) { s = g_src[gw]; d = g_dst[gw]; }
    else              { s = (int)(gw - N_EDGES); d = s; }
    #pragma unroll
    for (int h = 0; h < 4; ++h) {
        float l = leaky(g_asrc1[s * 4 + h] + g_adst1[d * 4 + h]);
        float alpha = __expf(l) / g_denom1[d * 4 + h];
        int c = h * 32 + lane;
        atomicAdd(&g_out1[d * HC1 + c], g_h1[s * HC1 + c] * alpha);
    }
}

// GEMM2: h2 = elu(out1 + b1) @ W2  (50000x128 @ 128x32), fused alpha2 epilogue.
// blockDim = 128; each warp processes one row at a time.
__global__ void k_gemm2(const float* __restrict__ W2, const float* __restrict__ b1,
                        const float* __restrict__ a_src2, const float* __restrict__ a_dst2) {
    __shared__ float Ws[HC1 * C2];     // 16 KB
    __shared__ float hs[4][HC1];
    int t = threadIdx.x;
    int lane = t & 31;
    int w = t >> 5;
    for (int i = t; i < HC1 * C2; i += 128) Ws[i] = W2[i];
    __syncthreads();
    float as = a_src2[lane];
    float ad = a_dst2[lane];
    for (int it = 0; it < 8; ++it) {
        int row = blockIdx.x * 32 + it * 4 + w;
        if (row < N_NODES) {
            #pragma unroll
            for (int j = 0; j < 4; ++j) {
                float v = g_out1[row * HC1 + j * 32 + lane] + b1[j * 32 + lane];
                v = v > 0.0f ? v : (__expf(v) - 1.0f);   // ELU
                hs[w][j * 32 + lane] = v;
            }
            __syncwarp();
            float acc = 0.0f;
            #pragma unroll
            for (int k = 0; k < HC1; ++k) acc += hs[w][k] * Ws[k * C2 + lane];
            g_h2[row * C2 + lane] = acc;
            float vs = acc * as, vd = acc * ad;
            #pragma unroll
            for (int o = 16; o > 0; o >>= 1) {
                vs += __shfl_xor_sync(0xffffffffu, vs, o);
                vd += __shfl_xor_sync(0xffffffffu, vd, o);
            }
            if (lane == 0) {
                g_asrc2[row] = vs;
                g_adst2[row] = vd;
            }
            __syncwarp();
        }
    }
}

__global__ void k_edge_den2() {
    int e = blockIdx.x * blockDim.x + threadIdx.x;
    if (e >= N_EDGES_T) return;
    int s, d;
    if (e < N_EDGES) { s = g_src[e]; d = g_dst[e]; }
    else             { s = e - N_EDGES; d = s; }
    float ex = __expf(leaky(g_asrc2[s] + g_adst2[d]));
    atomicAdd(&g_denom2[d], ex);
}

__global__ void k_edge_agg2() {
    long long gtid = (long long)blockIdx.x * blockDim.x + threadIdx.x;
    long long gw = gtid >> 5;
    int lane = threadIdx.x & 31;
    if (gw >= N_EDGES_T) return;
    int s, d;
    if (gw < N_EDGES) { s = g_src[gw]; d = g_dst[gw]; }
    else              { s = (int)(gw - N_EDGES); d = s; }
    float l = leaky(g_asrc2[s] + g_adst2[d]);
    float alpha = __expf(l) / g_denom2[d];
    atomicAdd(&g_out2[d * C2 + lane], g_h2[s * C2 + lane] * alpha);
}

// Global mean pool: accumulate sums + counts.
__global__ void k_pool(const float* __restrict__ b2) {
    int i = blockIdx.x * blockDim.x + threadIdx.x;
    if (i >= N_NODES * C2) return;
    int n = i >> 5;
    int c = i & 31;
    int g = g_batch[n];
    atomicAdd(&g_gsum[g * C2 + c], g_out2[i] + b2[c]);
    if (c == 0) atomicAdd(&g_gcnt[g], 1.0f);
}

__global__ void k_final(float* __restrict__ out) {
    int i = blockIdx.x * blockDim.x + threadIdx.x;
    if (i < NG * C2) out[i] = g_gsum[i] / fmaxf(g_gcnt[i >> 5], 1.0f);
}

extern "C" void kernel_launch(void* const* d_in, const int* in_sizes, int n_in,
                              void* d_out, int out_size) {
    const float* x     = (const float*)d_in[0];
    const void*  ei    = d_in[1];
    const void*  batch = d_in[2];
    int i = 3;
    if (n_in > 3 && in_sizes[3] == 1) i = 4;   // skip num_graphs scalar if present
    const float* W1  = (const float*)d_in[i + 0];
    const float* as1 = (const float*)d_in[i + 1];
    const float* ad1 = (const float*)d_in[i + 2];
    const float* b1  = (const float*)d_in[i + 3];
    const float* W2  = (const float*)d_in[i + 4];
    const float* as2 = (const float*)d_in[i + 5];
    const float* ad2 = (const float*)d_in[i + 6];
    const float* b2  = (const float*)d_in[i + 7];
    float* out = (float*)d_out;

    k_init<<<4096, 256>>>();
    k_detect<<<1024, 256>>>((const long long*)ei, (const long long*)batch);
    k_decode<<<2048, 256>>>(ei, batch);
    k_gemm1<<<3125, 128>>>(x, W1, as1, ad1);
    k_edge_den1<<<(N_EDGES_T + 255) / 256, 256>>>();
    {
        long long thr = (long long)N_EDGES_T * 32;
        int blocks = (int)((thr + 255) / 256);
        k_edge_agg1<<<blocks, 256>>>();
    }
    k_gemm2<<<(N_NODES + 31) / 32, 128>>>(W2, b1, as2, ad2);
    k_edge_den2<<<(N_EDGES_T + 255) / 256, 256>>>();
    {
        long long thr = (long long)N_EDGES_T * 32;
        int blocks = (int)((thr + 255) / 256);
        k_edge_agg2<<<blocks, 256>>>();
    }
    k_pool<<<(N_NODES * C2 + 255) / 256, 256>>>(b2);
    k_final<<<(NG * C2 + 255) / 256, 256>>>(out);
}

// round 3
// speedup vs baseline: 1.5747x; 1.5747x over previous
#include <cuda_runtime.h>
#include <cuda_bf16.h>

// Problem constants (fixed by setup_inputs)
#define N_NODES 50000
#define N_EDGES 1600000
#define N_EDGES_T (N_EDGES + N_NODES)   // with self loops = 1,650,000
#define F_IN 64
#define HC1 128          // H1*C1 = 4*32
#define C2 32
#define NG 512

// Scratch (device globals — no allocation allowed)
__device__ float g_h1[N_NODES * HC1];
__device__ float g_asrc1[N_NODES * 4];
__device__ float g_adst1[N_NODES * 4];
__device__ float g_denom1[N_NODES * 4];
__device__ float g_out1[N_NODES * HC1];
__device__ float g_h2[N_NODES * C2];
__device__ float g_asrc2[N_NODES];
__device__ float g_adst2[N_NODES];
__device__ float g_denom2[N_NODES];
__device__ float g_out2[N_NODES * C2];
__device__ float g_gsum[NG * C2];
__device__ float g_gcnt[NG];

// Decoded indices (int32, robust to harness delivering int32 or int64)
__device__ int g_src[N_EDGES];
__device__ int g_dst[N_EDGES];
__device__ int g_batch[N_NODES];
__device__ int g_ei_not64;
__device__ int g_b_not64;

__device__ __forceinline__ void red_add_v4(float* addr, float a, float b, float c, float d) {
    asm volatile("red.global.add.v4.f32 [%0], {%1, %2, %3, %4};"
                 :: "l"(addr), "f"(a), "f"(b), "f"(c), "f"(d) : "memory");
}

__global__ void k_init() {
    int i = blockIdx.x * blockDim.x + threadIdx.x;
    int stride = gridDim.x * blockDim.x;
    for (int j = i; j < N_NODES * HC1; j += stride) g_out1[j] = 0.0f;
    for (int j = i; j < N_NODES * C2;  j += stride) g_out2[j] = 0.0f;
    for (int j = i; j < N_NODES * 4;   j += stride) g_denom1[j] = 0.0f;
    for (int j = i; j < N_NODES;       j += stride) g_denom2[j] = 0.0f;
    if (i < NG * C2) g_gsum[i] = 0.0f;
    if (i < NG)      g_gcnt[i] = 0.0f;
    if (i == 0) { g_ei_not64 = 0; g_b_not64 = 0; }
}

// Detect whether edge_index / batch buffers hold int64 or int32 (see R2 notes).
__global__ void k_detect(const long long* __restrict__ ei,
                         const long long* __restrict__ batch) {
    int i = blockIdx.x * blockDim.x + threadIdx.x;
    int stride = gridDim.x * blockDim.x;
    for (int j = i; j < N_EDGES; j += stride) {
        long long v = ei[j];
        if (v < 0 || v >= N_NODES) { g_ei_not64 = 1; break; }
    }
    for (int j = i; j < N_NODES / 2; j += stride) {
        long long v = batch[j];
        if (v < 0 || v >= NG) { g_b_not64 = 1; break; }
    }
}

__global__ void k_decode(const void* __restrict__ ei, const void* __restrict__ batch) {
    int i = blockIdx.x * blockDim.x + threadIdx.x;
    int stride = gridDim.x * blockDim.x;
    bool e64 = (g_ei_not64 == 0);
    bool b64 = (g_b_not64 == 0);
    const long long* eL = (const long long*)ei;
    const int*       eI = (const int*)ei;
    const long long* bL = (const long long*)batch;
    const int*       bI = (const int*)batch;
    for (int j = i; j < N_EDGES; j += stride) {
        g_src[j] = e64 ? (int)eL[j]           : eI[j];
        g_dst[j] = e64 ? (int)eL[N_EDGES + j] : eI[N_EDGES + j];
    }
    for (int j = i; j < N_NODES; j += stride) {
        g_batch[j] = b64 ? (int)bL[j] : bI[j];
    }
}

// GEMM1: h1 = x @ W1  (50000x64 @ 64x128), register-blocked 8 rows/thread,
// fused per-head alpha epilogue. blockDim=128, 16 rows/block (2 subtiles of 8).
__global__ void k_gemm1(const float* __restrict__ x, const float* __restrict__ W1,
                        const float* __restrict__ a_src, const float* __restrict__ a_dst) {
    __shared__ float Ws[F_IN * HC1];   // 32 KB
    __shared__ float xs[F_IN][8];      // transposed x tile: [k][row], 2 KB
    int t = threadIdx.x;
    for (int i = t; i < F_IN * HC1; i += 128) Ws[i] = W1[i];
    float av_s = a_src[t];
    float av_d = a_dst[t];
    int head = t >> 5;
    #pragma unroll
    for (int sub = 0; sub < 2; ++sub) {
        int base = blockIdx.x * 16 + sub * 8;
        __syncthreads();
        for (int i = t; i < 8 * F_IN; i += 128) {   // 512 elems, 4 per thread
            int r = i >> 6, k = i & 63;
            xs[k][r] = x[(base + r) * F_IN + k];
        }
        __syncthreads();
        float acc[8] = {0,0,0,0,0,0,0,0};
        #pragma unroll
        for (int k = 0; k < F_IN; ++k) {
            float w = Ws[k * HC1 + t];
            float4 a = *(const float4*)&xs[k][0];   // broadcast LDS.128
            float4 b = *(const float4*)&xs[k][4];
            acc[0] += a.x * w; acc[1] += a.y * w; acc[2] += a.z * w; acc[3] += a.w * w;
            acc[4] += b.x * w; acc[5] += b.y * w; acc[6] += b.z * w; acc[7] += b.w * w;
        }
        #pragma unroll
        for (int r = 0; r < 8; ++r) {
            int row = base + r;
            g_h1[row * HC1 + t] = acc[r];
            float vs = acc[r] * av_s, vd = acc[r] * av_d;
            #pragma unroll
            for (int o = 16; o > 0; o >>= 1) {
                vs += __shfl_xor_sync(0xffffffffu, vs, o);
                vd += __shfl_xor_sync(0xffffffffu, vd, o);
            }
            if ((t & 31) == 0) {
                g_asrc1[row * 4 + head] = vs;
                g_adst1[row * 4 + head] = vd;
            }
        }
    }
}

__device__ __forceinline__ float leaky(float v) {
    return v > 0.0f ? v : 0.2f * v;
}

// Layer-1 edge denominator: one thread per edge, 4 heads via one v4 reduction.
__global__ void k_edge_den1() {
    int e = blockIdx.x * blockDim.x + threadIdx.x;
    if (e >= N_EDGES_T) return;
    int s, d;
    if (e < N_EDGES) { s = g_src[e]; d = g_dst[e]; }
    else             { s = e - N_EDGES; d = s; }
    float4 as = *(const float4*)&g_asrc1[s * 4];
    float4 ad = *(const float4*)&g_adst1[d * 4];
    red_add_v4(&g_denom1[d * 4],
               __expf(leaky(as.x + ad.x)), __expf(leaky(as.y + ad.y)),
               __expf(leaky(as.z + ad.z)), __expf(leaky(as.w + ad.w)));
}

// Layer-1 aggregation: one warp per edge; lane handles 4 channels via v4 red.
// Channels 4*lane..4*lane+3 are within head (lane>>3).
__global__ void k_edge_agg1() {
    long long gtid = (long long)blockIdx.x * blockDim.x + threadIdx.x;
    long long gw = gtid >> 5;
    int lane = threadIdx.x & 31;
    if (gw >= N_EDGES_T) return;
    int s, d;
    if (gw < N_EDGES) { s = g_src[gw]; d = g_dst[gw]; }
    else              { s = (int)(gw - N_EDGES); d = s; }
    int h = lane >> 3;
    float l = leaky(g_asrc1[s * 4 + h] + g_adst1[d * 4 + h]);
    float alpha = __expf(l) / g_denom1[d * 4 + h];
    float4 hv = *(const float4*)&g_h1[s * HC1 + lane * 4];
    red_add_v4(&g_out1[d * HC1 + lane * 4],
               hv.x * alpha, hv.y * alpha, hv.z * alpha, hv.w * alpha);
}

// GEMM2: h2 = elu(out1 + b1) @ W2  (50000x128 @ 128x32), fused alpha2 epilogue.
__global__ void k_gemm2(const float* __restrict__ W2, const float* __restrict__ b1,
                        const float* __restrict__ a_src2, const float* __restrict__ a_dst2) {
    __shared__ float Ws[HC1 * C2];     // 16 KB
    __shared__ float hs[4][HC1];
    int t = threadIdx.x;
    int lane = t & 31;
    int w = t >> 5;
    for (int i = t; i < HC1 * C2; i += 128) Ws[i] = W2[i];
    __syncthreads();
    float as = a_src2[lane];
    float ad = a_dst2[lane];
    for (int it = 0; it < 8; ++it) {
        int row = blockIdx.x * 32 + it * 4 + w;
        if (row < N_NODES) {
            #pragma unroll
            for (int j = 0; j < 4; ++j) {
                float v = g_out1[row * HC1 + j * 32 + lane] + b1[j * 32 + lane];
                v = v > 0.0f ? v : (__expf(v) - 1.0f);   // ELU
                hs[w][j * 32 + lane] = v;
            }
            __syncwarp();
            float acc = 0.0f;
            #pragma unroll
            for (int k = 0; k < HC1; ++k) acc += hs[w][k] * Ws[k * C2 + lane];
            g_h2[row * C2 + lane] = acc;
            float vs = acc * as, vd = acc * ad;
            #pragma unroll
            for (int o = 16; o > 0; o >>= 1) {
                vs += __shfl_xor_sync(0xffffffffu, vs, o);
                vd += __shfl_xor_sync(0xffffffffu, vd, o);
            }
            if (lane == 0) {
                g_asrc2[row] = vs;
                g_adst2[row] = vd;
            }
            __syncwarp();
        }
    }
}

__global__ void k_edge_den2() {
    int e = blockIdx.x * blockDim.x + threadIdx.x;
    if (e >= N_EDGES_T) return;
    int s, d;
    if (e < N_EDGES) { s = g_src[e]; d = g_dst[e]; }
    else             { s = e - N_EDGES; d = s; }
    float ex = __expf(leaky(g_asrc2[s] + g_adst2[d]));
    atomicAdd(&g_denom2[d], ex);
}

// Layer-2 aggregation: 8 threads per edge, each covers 4 channels via v4 red.
__global__ void k_edge_agg2() {
    long long gtid = (long long)blockIdx.x * blockDim.x + threadIdx.x;
    long long ge = gtid >> 3;
    int q = threadIdx.x & 7;
    if (ge >= N_EDGES_T) return;
    int s, d;
    if (ge < N_EDGES) { s = g_src[ge]; d = g_dst[ge]; }
    else              { s = (int)(ge - N_EDGES); d = s; }
    float l = leaky(g_asrc2[s] + g_adst2[d]);
    float alpha = __expf(l) / g_denom2[d];
    float4 hv = *(const float4*)&g_h2[s * C2 + q * 4];
    red_add_v4(&g_out2[d * C2 + q * 4],
               hv.x * alpha, hv.y * alpha, hv.z * alpha, hv.w * alpha);
}

// Global mean pool: 8 threads per node, v4 reductions; lane q==0 adds count.
__global__ void k_pool(const float* __restrict__ b2) {
    int i = blockIdx.x * blockDim.x + threadIdx.x;
    if (i >= N_NODES * 8) return;
    int n = i >> 3;
    int q = i & 7;
    int g = g_batch[n];
    float4 v = *(const float4*)&g_out2[n * C2 + q * 4];
    float4 bb = *(const float4*)&b2[q * 4];
    red_add_v4(&g_gsum[g * C2 + q * 4], v.x + bb.x, v.y + bb.y, v.z + bb.z, v.w + bb.w);
    if (q == 0) atomicAdd(&g_gcnt[g], 1.0f);
}

__global__ void k_final(float* __restrict__ out) {
    int i = blockIdx.x * blockDim.x + threadIdx.x;
    if (i < NG * C2) out[i] = g_gsum[i] / fmaxf(g_gcnt[i >> 5], 1.0f);
}

extern "C" void kernel_launch(void* const* d_in, const int* in_sizes, int n_in,
                              void* d_out, int out_size) {
    const float* x     = (const float*)d_in[0];
    const void*  ei    = d_in[1];
    const void*  batch = d_in[2];
    int i = 3;
    if (n_in > 3 && in_sizes[3] == 1) i = 4;   // skip num_graphs scalar if present
    const float* W1  = (const float*)d_in[i + 0];
    const float* as1 = (const float*)d_in[i + 1];
    const float* ad1 = (const float*)d_in[i + 2];
    const float* b1  = (const float*)d_in[i + 3];
    const float* W2  = (const float*)d_in[i + 4];
    const float* as2 = (const float*)d_in[i + 5];
    const float* ad2 = (const float*)d_in[i + 6];
    const float* b2  = (const float*)d_in[i + 7];
    float* out = (float*)d_out;

    k_init<<<4096, 256>>>();
    k_detect<<<1024, 256>>>((const long long*)ei, (const long long*)batch);
    k_decode<<<2048, 256>>>(ei, batch);
    k_gemm1<<<3125, 128>>>(x, W1, as1, ad1);
    k_edge_den1<<<(N_EDGES_T + 255) / 256, 256>>>();
    {
        long long thr = (long long)N_EDGES_T * 32;
        int blocks = (int)((thr + 255) / 256);
        k_edge_agg1<<<blocks, 256>>>();
    }
    k_gemm2<<<(N_NODES + 31) / 32, 128>>>(W2, b1, as2, ad2);
    k_edge_den2<<<(N_EDGES_T + 255) / 256, 256>>>();
    {
        long long thr = (long long)N_EDGES_T * 8;
        int blocks = (int)((thr + 255) / 256);
        k_edge_agg2<<<blocks, 256>>>();
    }
    k_pool<<<(N_NODES * 8 + 255) / 256, 256>>>(b2);
    k_final<<<(NG * C2 + 255) / 256, 256>>>(out);
}

// round 4
// speedup vs baseline: 2.0864x; 1.3250x over previous
#include <cuda_runtime.h>
#include <cuda_bf16.h>

// Problem constants (fixed by setup_inputs)
#define N_NODES 50000
#define N_EDGES 1600000
#define N_EDGES_T (N_EDGES + N_NODES)   // with self loops = 1,650,000
#define F_IN 64
#define HC1 128          // H1*C1 = 4*32
#define C2 32
#define NG 512

// Scratch (device globals — no allocation allowed)
__device__ float g_h1[N_NODES * HC1];
__device__ float g_asrc1[N_NODES * 4];
__device__ float g_adst1[N_NODES * 4];
__device__ float g_out1[N_NODES * HC1];
__device__ float g_h2[N_NODES * C2];
__device__ float g_asrc2[N_NODES];
__device__ float g_adst2[N_NODES];
__device__ float g_out2[N_NODES * C2];
__device__ float g_gsum[NG * C2];
__device__ float g_gcnt[NG];

// Decoded indices + CSR by dst
__device__ int g_src[N_EDGES];
__device__ int g_dst[N_EDGES];
__device__ int g_batch[N_NODES];
__device__ int g_deg[N_NODES];
__device__ int g_off[N_NODES + 1];
__device__ int g_pos[N_NODES];
__device__ int g_ssorted[N_EDGES_T];   // src node per dst-sorted edge
__device__ int g_ei_not64;
__device__ int g_b_not64;

__device__ __forceinline__ void red_add_v4(float* addr, float a, float b, float c, float d) {
    asm volatile("red.global.add.v4.f32 [%0], {%1, %2, %3, %4};"
                 :: "l"(addr), "f"(a), "f"(b), "f"(c), "f"(d) : "memory");
}

__device__ __forceinline__ float leaky(float v) {
    return v > 0.0f ? v : 0.2f * v;
}

__global__ void k_init() {
    int i = blockIdx.x * blockDim.x + threadIdx.x;
    int stride = gridDim.x * blockDim.x;
    for (int j = i; j < N_NODES; j += stride) g_deg[j] = 0;
    if (i < NG * C2) g_gsum[i] = 0.0f;
    if (i < NG)      g_gcnt[i] = 0.0f;
    if (i == 0) { g_ei_not64 = 0; g_b_not64 = 0; }
}

// Detect whether edge_index / batch buffers hold int64 or int32.
// Only reads int64 words that are in-bounds under EITHER interpretation.
__global__ void k_detect(const long long* __restrict__ ei,
                         const long long* __restrict__ batch) {
    int i = blockIdx.x * blockDim.x + threadIdx.x;
    int stride = gridDim.x * blockDim.x;
    for (int j = i; j < N_EDGES; j += stride) {
        long long v = ei[j];
        if (v < 0 || v >= N_NODES) { g_ei_not64 = 1; break; }
    }
    for (int j = i; j < N_NODES / 2; j += stride) {
        long long v = batch[j];
        if (v < 0 || v >= NG) { g_b_not64 = 1; break; }
    }
}

__global__ void k_decode(const void* __restrict__ ei, const void* __restrict__ batch) {
    int i = blockIdx.x * blockDim.x + threadIdx.x;
    int stride = gridDim.x * blockDim.x;
    bool e64 = (g_ei_not64 == 0);
    bool b64 = (g_b_not64 == 0);
    const long long* eL = (const long long*)ei;
    const int*       eI = (const int*)ei;
    const long long* bL = (const long long*)batch;
    const int*       bI = (const int*)batch;
    for (int j = i; j < N_EDGES; j += stride) {
        g_src[j] = e64 ? (int)eL[j]           : eI[j];
        g_dst[j] = e64 ? (int)eL[N_EDGES + j] : eI[N_EDGES + j];
    }
    for (int j = i; j < N_NODES; j += stride) {
        g_batch[j] = b64 ? (int)bL[j] : bI[j];
    }
}

__global__ void k_hist() {
    int e = blockIdx.x * blockDim.x + threadIdx.x;
    if (e >= N_EDGES_T) return;
    int d = (e < N_EDGES) ? g_dst[e] : (e - N_EDGES);
    atomicAdd(&g_deg[d], 1);
}

// Exclusive prefix sum of degrees; single block of 1024 threads.
__global__ void k_scan() {
    __shared__ int sums[1024];
    int t = threadIdx.x;
    const int CH = (N_NODES + 1023) / 1024;   // 49
    int start = t * CH;
    int end = start + CH; if (end > N_NODES) end = N_NODES;
    int local = 0;
    for (int i = start; i < end; ++i) local += g_deg[i];
    sums[t] = local;
    __syncthreads();
    #pragma unroll
    for (int off = 1; off < 1024; off <<= 1) {
        int v = (t >= off) ? sums[t - off] : 0;
        __syncthreads();
        sums[t] += v;
        __syncthreads();
    }
    int base = (t == 0) ? 0 : sums[t - 1];
    for (int i = start; i < end; ++i) {
        int d = g_deg[i];
        g_off[i] = base;
        g_pos[i] = base;
        base += d;
    }
    if (t == 1023) g_off[N_NODES] = base;
}

__global__ void k_scatter() {
    int e = blockIdx.x * blockDim.x + threadIdx.x;
    if (e >= N_EDGES_T) return;
    int s, d;
    if (e < N_EDGES) { s = g_src[e]; d = g_dst[e]; }
    else             { s = e - N_EDGES; d = s; }
    int p = atomicAdd(&g_pos[d], 1);
    g_ssorted[p] = s;
}

// GEMM1: h1 = x @ W1 (50000x64 @ 64x128), 16 rows/thread register blocking,
// fused per-head alpha epilogue. blockDim=128 (thread t = output column t).
__global__ void k_gemm1(const float* __restrict__ x, const float* __restrict__ W1,
                        const float* __restrict__ a_src, const float* __restrict__ a_dst) {
    __shared__ float Ws[F_IN * HC1];   // 32 KB
    __shared__ float xs[F_IN][20];     // transposed x tile [k][row], padded
    int t = threadIdx.x;
    for (int i = t; i < F_IN * HC1; i += 128) Ws[i] = W1[i];
    float av_s = a_src[t];
    float av_d = a_dst[t];
    int head = t >> 5;
    int base = blockIdx.x * 16;
    // Load x tile transposed: 16 rows x 64 cols; coalesced 64-wide row reads.
    {
        int k = t & 63;
        int r0 = t >> 6;            // 0..1
        #pragma unroll
        for (int j = 0; j < 8; ++j) {
            int r = r0 + j * 2;
            xs[k][r] = x[(base + r) * F_IN + k];
        }
    }
    __syncthreads();
    float acc[16];
    #pragma unroll
    for (int r = 0; r < 16; ++r) acc[r] = 0.0f;
    #pragma unroll
    for (int k = 0; k < F_IN; ++k) {
        float w = Ws[k * HC1 + t];
        float4 a = *(const float4*)&xs[k][0];
        float4 b = *(const float4*)&xs[k][4];
        float4 c = *(const float4*)&xs[k][8];
        float4 d = *(const float4*)&xs[k][12];
        acc[0]  += a.x * w; acc[1]  += a.y * w; acc[2]  += a.z * w; acc[3]  += a.w * w;
        acc[4]  += b.x * w; acc[5]  += b.y * w; acc[6]  += b.z * w; acc[7]  += b.w * w;
        acc[8]  += c.x * w; acc[9]  += c.y * w; acc[10] += c.z * w; acc[11] += c.w * w;
        acc[12] += d.x * w; acc[13] += d.y * w; acc[14] += d.z * w; acc[15] += d.w * w;
    }
    #pragma unroll
    for (int r = 0; r < 16; ++r) {
        int row = base + r;
        g_h1[row * HC1 + t] = acc[r];
        float vs = acc[r] * av_s, vd = acc[r] * av_d;
        #pragma unroll
        for (int o = 16; o > 0; o >>= 1) {
            vs += __shfl_xor_sync(0xffffffffu, vs, o);
            vd += __shfl_xor_sync(0xffffffffu, vd, o);
        }
        if ((t & 31) == 0) {
            g_asrc1[row * 4 + head] = vs;
            g_adst1[row * 4 + head] = vd;
        }
    }
}

// Fused layer-1 softmax + aggregation: one warp per dst node, single pass.
// Lane l accumulates channels 4l..4l+3 plus the per-head denom; normalize at end.
__global__ void k_agg1() {
    int gw = (blockIdx.x * blockDim.x + threadIdx.x) >> 5;
    int lane = threadIdx.x & 31;
    if (gw >= N_NODES) return;
    int d = gw;
    int h = lane >> 3;
    float adh = g_adst1[d * 4 + h];
    int beg = g_off[d], end = g_off[d + 1];
    float4 acc = make_float4(0.f, 0.f, 0.f, 0.f);
    float denom = 0.0f;
    for (int j = beg; j < end; ++j) {
        int s = g_ssorted[j];
        float ex = __expf(leaky(g_asrc1[s * 4 + h] + adh));
        float4 hv = *(const float4*)&g_h1[s * HC1 + lane * 4];
        acc.x += ex * hv.x; acc.y += ex * hv.y;
        acc.z += ex * hv.z; acc.w += ex * hv.w;
        denom += ex;
    }
    float inv = 1.0f / denom;
    acc.x *= inv; acc.y *= inv; acc.z *= inv; acc.w *= inv;
    *(float4*)&g_out1[d * HC1 + lane * 4] = acc;
}

// GEMM2: h2 = elu(out1 + b1) @ W2 (50000x128 @ 128x32), fused alpha2 epilogue.
__global__ void k_gemm2(const float* __restrict__ W2, const float* __restrict__ b1,
                        const float* __restrict__ a_src2, const float* __restrict__ a_dst2) {
    __shared__ float Ws[HC1 * C2];     // 16 KB
    __shared__ float hs[4][HC1];
    int t = threadIdx.x;
    int lane = t & 31;
    int w = t >> 5;
    for (int i = t; i < HC1 * C2; i += 128) Ws[i] = W2[i];
    __syncthreads();
    float as = a_src2[lane];
    float ad = a_dst2[lane];
    for (int it = 0; it < 8; ++it) {
        int row = blockIdx.x * 32 + it * 4 + w;
        if (row < N_NODES) {
            #pragma unroll
            for (int j = 0; j < 4; ++j) {
                float v = g_out1[row * HC1 + j * 32 + lane] + b1[j * 32 + lane];
                v = v > 0.0f ? v : (__expf(v) - 1.0f);   // ELU
                hs[w][j * 32 + lane] = v;
            }
            __syncwarp();
            float acc = 0.0f;
            #pragma unroll
            for (int k = 0; k < HC1; ++k) acc += hs[w][k] * Ws[k * C2 + lane];
            g_h2[row * C2 + lane] = acc;
            float vs = acc * as, vd = acc * ad;
            #pragma unroll
            for (int o = 16; o > 0; o >>= 1) {
                vs += __shfl_xor_sync(0xffffffffu, vs, o);
                vd += __shfl_xor_sync(0xffffffffu, vd, o);
            }
            if (lane == 0) {
                g_asrc2[row] = vs;
                g_adst2[row] = vd;
            }
            __syncwarp();
        }
    }
}

// Fused layer-2 softmax + aggregation: one warp per dst node, lane = channel.
__global__ void k_agg2() {
    int gw = (blockIdx.x * blockDim.x + threadIdx.x) >> 5;
    int lane = threadIdx.x & 31;
    if (gw >= N_NODES) return;
    int d = gw;
    float ad = g_adst2[d];
    int beg = g_off[d], end = g_off[d + 1];
    float acc = 0.0f, denom = 0.0f;
    for (int j = beg; j < end; ++j) {
        int s = g_ssorted[j];
        float ex = __expf(leaky(g_asrc2[s] + ad));
        acc += ex * g_h2[s * C2 + lane];
        denom += ex;
    }
    g_out2[d * C2 + lane] = acc / denom;
}

// Global mean pool: 8 threads per node, v4 reductions; q==0 adds count.
__global__ void k_pool(const float* __restrict__ b2) {
    int i = blockIdx.x * blockDim.x + threadIdx.x;
    if (i >= N_NODES * 8) return;
    int n = i >> 3;
    int q = i & 7;
    int g = g_batch[n];
    float4 v = *(const float4*)&g_out2[n * C2 + q * 4];
    float4 bb = *(const float4*)&b2[q * 4];
    red_add_v4(&g_gsum[g * C2 + q * 4], v.x + bb.x, v.y + bb.y, v.z + bb.z, v.w + bb.w);
    if (q == 0) atomicAdd(&g_gcnt[g], 1.0f);
}

__global__ void k_final(float* __restrict__ out) {
    int i = blockIdx.x * blockDim.x + threadIdx.x;
    if (i < NG * C2) out[i] = g_gsum[i] / fmaxf(g_gcnt[i >> 5], 1.0f);
}

extern "C" void kernel_launch(void* const* d_in, const int* in_sizes, int n_in,
                              void* d_out, int out_size) {
    const float* x     = (const float*)d_in[0];
    const void*  ei    = d_in[1];
    const void*  batch = d_in[2];
    int i = 3;
    if (n_in > 3 && in_sizes[3] == 1) i = 4;   // skip num_graphs scalar if present
    const float* W1  = (const float*)d_in[i + 0];
    const float* as1 = (const float*)d_in[i + 1];
    const float* ad1 = (const float*)d_in[i + 2];
    const float* b1  = (const float*)d_in[i + 3];
    const float* W2  = (const float*)d_in[i + 4];
    const float* as2 = (const float*)d_in[i + 5];
    const float* ad2 = (const float*)d_in[i + 6];
    const float* b2  = (const float*)d_in[i + 7];
    float* out = (float*)d_out;

    k_init<<<512, 256>>>();
    k_detect<<<1024, 256>>>((const long long*)ei, (const long long*)batch);
    k_decode<<<2048, 256>>>(ei, batch);
    k_hist<<<(N_EDGES_T + 255) / 256, 256>>>();
    k_scan<<<1, 1024>>>();
    k_scatter<<<(N_EDGES_T + 255) / 256, 256>>>();
    k_gemm1<<<3125, 128>>>(x, W1, as1, ad1);
    k_agg1<<<(N_NODES * 32 + 255) / 256, 256>>>();
    k_gemm2<<<(N_NODES + 31) / 32, 128>>>(W2, b1, as2, ad2);
    k_agg2<<<(N_NODES * 32 + 255) / 256, 256>>>();
    k_pool<<<(N_NODES * 8 + 255) / 256, 256>>>(b2);
    k_final<<<(NG * C2 + 255) / 256, 256>>>(out);
}

// round 5
// speedup vs baseline: 2.3249x; 1.1143x over previous
#include <cuda_runtime.h>
#include <cuda_fp16.h>
#include <cuda_bf16.h>

// Problem constants (fixed by setup_inputs)
#define N_NODES 50000
#define N_EDGES 1600000
#define N_EDGES_T (N_EDGES + N_NODES)   // with self loops = 1,650,000
#define F_IN 64
#define HC1 128          // H1*C1 = 4*32
#define C2 32
#define NG 512

// Scratch (device globals — no allocation allowed)
__device__ __half g_h1h[N_NODES * HC1];   // fp16 messages, layer 1
__device__ __half g_h2h[N_NODES * C2];    // fp16 messages, layer 2
__device__ float g_asrc1[N_NODES * 4];
__device__ float g_adst1[N_NODES * 4];
__device__ float g_asrc2[N_NODES];
__device__ float g_adst2[N_NODES];
__device__ float g_gsum[NG * C2];
__device__ float g_gcnt[NG];

// Decoded indices + CSR by dst
__device__ int g_src[N_EDGES];
__device__ int g_dst[N_EDGES];
__device__ int g_batch[N_NODES];
__device__ int g_deg[N_NODES];
__device__ int g_off[N_NODES + 1];
__device__ int g_pos[N_NODES];
__device__ int g_ssorted[N_EDGES_T];
__device__ int g_ei_not64;
__device__ int g_b_not64;

__device__ __forceinline__ float leaky(float v) {
    return v > 0.0f ? v : 0.2f * v;
}
__device__ __forceinline__ float eluf(float v) {
    return v > 0.0f ? v : (__expf(v) - 1.0f);
}

__global__ void k_init() {
    int i = blockIdx.x * blockDim.x + threadIdx.x;
    int stride = gridDim.x * blockDim.x;
    for (int j = i; j < N_NODES; j += stride) g_deg[j] = 1;   // self loop
    if (i < NG * C2) g_gsum[i] = 0.0f;
    if (i < NG)      g_gcnt[i] = 0.0f;
    if (i == 0) { g_ei_not64 = 0; g_b_not64 = 0; }
}

// Sampled dtype detection. Samples are in-bounds under EITHER interpretation.
// For batch (sorted, small values at the front) we sample the TAIL of the
// safe half-range: under int32 data the packed high word there is ~511 != 0.
__global__ void k_detect(const long long* __restrict__ ei,
                         const long long* __restrict__ batch) {
    int i = blockIdx.x * blockDim.x + threadIdx.x;
    if (i < 4096) {
        long long v = ei[(long long)i * (N_EDGES / 4096)];
        if (v < 0 || v >= N_NODES) g_ei_not64 = 1;
    }
    if (i < 1000) {
        long long v = batch[N_NODES / 2 - 1 - i];
        if (v < 0 || v >= NG) g_b_not64 = 1;
    }
}

// Fused decode (int64|int32 -> int32) + dst histogram.
__global__ void k_decodehist(const void* __restrict__ ei, const void* __restrict__ batch) {
    int i = blockIdx.x * blockDim.x + threadIdx.x;
    int stride = gridDim.x * blockDim.x;
    bool e64 = (g_ei_not64 == 0);
    bool b64 = (g_b_not64 == 0);
    const long long* eL = (const long long*)ei;
    const int*       eI = (const int*)ei;
    const long long* bL = (const long long*)batch;
    const int*       bI = (const int*)batch;
    for (int j = i; j < N_EDGES; j += stride) {
        int s = e64 ? (int)eL[j]           : eI[j];
        int d = e64 ? (int)eL[N_EDGES + j] : eI[N_EDGES + j];
        g_src[j] = s;
        g_dst[j] = d;
        atomicAdd(&g_deg[d], 1);
    }
    for (int j = i; j < N_NODES; j += stride) {
        g_batch[j] = b64 ? (int)bL[j] : bI[j];
    }
}

// Exclusive prefix sum of degrees; single block of 1024 threads.
__global__ void k_scan() {
    __shared__ int sums[1024];
    int t = threadIdx.x;
    const int CH = (N_NODES + 1023) / 1024;   // 49
    int start = t * CH;
    int end = start + CH; if (end > N_NODES) end = N_NODES;
    int local = 0;
    for (int i = start; i < end; ++i) local += g_deg[i];
    sums[t] = local;
    __syncthreads();
    #pragma unroll
    for (int off = 1; off < 1024; off <<= 1) {
        int v = (t >= off) ? sums[t - off] : 0;
        __syncthreads();
        sums[t] += v;
        __syncthreads();
    }
    int base = (t == 0) ? 0 : sums[t - 1];
    for (int i = start; i < end; ++i) {
        int d = g_deg[i];
        g_off[i] = base;
        g_pos[i] = base;
        base += d;
    }
    if (t == 1023) g_off[N_NODES] = base;
}

__global__ void k_scatter() {
    int e = blockIdx.x * blockDim.x + threadIdx.x;
    if (e >= N_EDGES_T) return;
    int s, d;
    if (e < N_EDGES) { s = g_src[e]; d = g_dst[e]; }
    else             { s = e - N_EDGES; d = s; }
    int p = atomicAdd(&g_pos[d], 1);
    g_ssorted[p] = s;
}

// GEMM1: h1 = x @ W1 (50000x64 @ 64x128), 16 rows/thread register blocking,
// fused per-head alpha epilogue (fp32 — matches reference), fp16 h1 store.
__global__ void k_gemm1(const float* __restrict__ x, const float* __restrict__ W1,
                        const float* __restrict__ a_src, const float* __restrict__ a_dst) {
    __shared__ float Ws[F_IN * HC1];   // 32 KB
    __shared__ float xs[F_IN][20];     // transposed x tile [k][row], padded
    int t = threadIdx.x;
    for (int i = t; i < F_IN * HC1; i += 128) Ws[i] = W1[i];
    float av_s = a_src[t];
    float av_d = a_dst[t];
    int head = t >> 5;
    int base = blockIdx.x * 16;
    {
        int k = t & 63;
        int r0 = t >> 6;
        #pragma unroll
        for (int j = 0; j < 8; ++j) {
            int r = r0 + j * 2;
            xs[k][r] = x[(base + r) * F_IN + k];
        }
    }
    __syncthreads();
    float acc[16];
    #pragma unroll
    for (int r = 0; r < 16; ++r) acc[r] = 0.0f;
    #pragma unroll
    for (int k = 0; k < F_IN; ++k) {
        float w = Ws[k * HC1 + t];
        float4 a = *(const float4*)&xs[k][0];
        float4 b = *(const float4*)&xs[k][4];
        float4 c = *(const float4*)&xs[k][8];
        float4 d = *(const float4*)&xs[k][12];
        acc[0]  += a.x * w; acc[1]  += a.y * w; acc[2]  += a.z * w; acc[3]  += a.w * w;
        acc[4]  += b.x * w; acc[5]  += b.y * w; acc[6]  += b.z * w; acc[7]  += b.w * w;
        acc[8]  += c.x * w; acc[9]  += c.y * w; acc[10] += c.z * w; acc[11] += c.w * w;
        acc[12] += d.x * w; acc[13] += d.y * w; acc[14] += d.z * w; acc[15] += d.w * w;
    }
    #pragma unroll
    for (int r = 0; r < 16; ++r) {
        int row = base + r;
        g_h1h[row * HC1 + t] = __float2half_rn(acc[r]);
        float vs = acc[r] * av_s, vd = acc[r] * av_d;
        #pragma unroll
        for (int o = 16; o > 0; o >>= 1) {
            vs += __shfl_xor_sync(0xffffffffu, vs, o);
            vd += __shfl_xor_sync(0xffffffffu, vd, o);
        }
        if ((t & 31) == 0) {
            g_asrc1[row * 4 + head] = vs;
            g_adst1[row * 4 + head] = vd;
        }
    }
}

// Fused layer-1 softmax+aggregate + ELU + GEMM2 + alpha2 epilogue.
// One warp per dst node; 8 warps/block; 6250 blocks * 8 = 50000 exactly.
__global__ void __launch_bounds__(256) k_agg1g2(
        const float* __restrict__ b1, const float* __restrict__ W2,
        const float* __restrict__ a_src2, const float* __restrict__ a_dst2) {
    __shared__ float W2s[HC1 * C2];    // 16 KB
    __shared__ float hs[8][HC1];       // 4 KB: per-warp ELU'd row
    int t = threadIdx.x;
    int w = t >> 5;
    int lane = t & 31;
    for (int i = t; i < HC1 * C2; i += 256) W2s[i] = W2[i];
    __syncthreads();

    int d = blockIdx.x * 8 + w;
    int h = lane >> 3;
    float adh = g_adst1[d * 4 + h];
    int beg = g_off[d], end = g_off[d + 1];
    float4 acc = make_float4(0.f, 0.f, 0.f, 0.f);
    float den = 0.0f;
    int j = beg;
    for (; j + 2 <= end; j += 2) {
        int s0 = g_ssorted[j];
        int s1 = g_ssorted[j + 1];
        float a0 = g_asrc1[s0 * 4 + h];
        float a1 = g_asrc1[s1 * 4 + h];
        uint2 q0 = *(const uint2*)(g_h1h + s0 * HC1 + lane * 4);
        uint2 q1 = *(const uint2*)(g_h1h + s1 * HC1 + lane * 4);
        float ex0 = __expf(leaky(a0 + adh));
        float ex1 = __expf(leaky(a1 + adh));
        float2 v00 = __half22float2(*reinterpret_cast<__half2*>(&q0.x));
        float2 v01 = __half22float2(*reinterpret_cast<__half2*>(&q0.y));
        float2 v10 = __half22float2(*reinterpret_cast<__half2*>(&q1.x));
        float2 v11 = __half22float2(*reinterpret_cast<__half2*>(&q1.y));
        acc.x += ex0 * v00.x + ex1 * v10.x;
        acc.y += ex0 * v00.y + ex1 * v10.y;
        acc.z += ex0 * v01.x + ex1 * v11.x;
        acc.w += ex0 * v01.y + ex1 * v11.y;
        den += ex0 + ex1;
    }
    if (j < end) {
        int s0 = g_ssorted[j];
        float a0 = g_asrc1[s0 * 4 + h];
        uint2 q0 = *(const uint2*)(g_h1h + s0 * HC1 + lane * 4);
        float ex0 = __expf(leaky(a0 + adh));
        float2 v00 = __half22float2(*reinterpret_cast<__half2*>(&q0.x));
        float2 v01 = __half22float2(*reinterpret_cast<__half2*>(&q0.y));
        acc.x += ex0 * v00.x;
        acc.y += ex0 * v00.y;
        acc.z += ex0 * v01.x;
        acc.w += ex0 * v01.y;
        den += ex0;
    }
    float inv = 1.0f / den;
    int c0 = lane * 4;
    hs[w][c0 + 0] = eluf(acc.x * inv + b1[c0 + 0]);
    hs[w][c0 + 1] = eluf(acc.y * inv + b1[c0 + 1]);
    hs[w][c0 + 2] = eluf(acc.z * inv + b1[c0 + 2]);
    hs[w][c0 + 3] = eluf(acc.w * inv + b1[c0 + 3]);
    __syncwarp();

    // GEMM2 row: h2 = hs[w] @ W2 (128 -> 32); lane = output channel.
    float acc2 = 0.0f;
    #pragma unroll
    for (int k = 0; k < HC1; k += 4) {
        float4 hv = *(const float4*)&hs[w][k];
        acc2 += hv.x * W2s[(k + 0) * C2 + lane];
        acc2 += hv.y * W2s[(k + 1) * C2 + lane];
        acc2 += hv.z * W2s[(k + 2) * C2 + lane];
        acc2 += hv.w * W2s[(k + 3) * C2 + lane];
    }
    g_h2h[d * C2 + lane] = __float2half_rn(acc2);
    float vs = acc2 * a_src2[lane];
    float vd = acc2 * a_dst2[lane];
    #pragma unroll
    for (int o = 16; o > 0; o >>= 1) {
        vs += __shfl_xor_sync(0xffffffffu, vs, o);
        vd += __shfl_xor_sync(0xffffffffu, vd, o);
    }
    if (lane == 0) {
        g_asrc2[d] = vs;
        g_adst2[d] = vd;
    }
}

// Fused layer-2 softmax+aggregate + bias + global mean pool accumulation.
// One warp per dst node (lane = channel); 6250 blocks * 8 warps.
__global__ void __launch_bounds__(256) k_agg2p(const float* __restrict__ b2) {
    int t = threadIdx.x;
    int w = t >> 5;
    int lane = t & 31;
    int d = blockIdx.x * 8 + w;
    float ad = g_adst2[d];
    int beg = g_off[d], end = g_off[d + 1];
    float acc = 0.0f, den = 0.0f;
    int j = beg;
    for (; j + 2 <= end; j += 2) {
        int s0 = g_ssorted[j];
        int s1 = g_ssorted[j + 1];
        float a0 = g_asrc2[s0];
        float a1 = g_asrc2[s1];
        float h0 = __half2float(g_h2h[s0 * C2 + lane]);
        float h1 = __half2float(g_h2h[s1 * C2 + lane]);
        float ex0 = __expf(leaky(a0 + ad));
        float ex1 = __expf(leaky(a1 + ad));
        acc += ex0 * h0 + ex1 * h1;
        den += ex0 + ex1;
    }
    if (j < end) {
        int s0 = g_ssorted[j];
        float ex0 = __expf(leaky(g_asrc2[s0] + ad));
        acc += ex0 * __half2float(g_h2h[s0 * C2 + lane]);
        den += ex0;
    }
    float outc = acc / den + b2[lane];
    int g = g_batch[d];
    atomicAdd(&g_gsum[g * C2 + lane], outc);
    if (lane == 0) atomicAdd(&g_gcnt[g], 1.0f);
}

__global__ void k_final(float* __restrict__ out) {
    int i = blockIdx.x * blockDim.x + threadIdx.x;
    if (i < NG * C2) out[i] = g_gsum[i] / fmaxf(g_gcnt[i >> 5], 1.0f);
}

extern "C" void kernel_launch(void* const* d_in, const int* in_sizes, int n_in,
                              void* d_out, int out_size) {
    const float* x     = (const float*)d_in[0];
    const void*  ei    = d_in[1];
    const void*  batch = d_in[2];
    int i = 3;
    if (n_in > 3 && in_sizes[3] == 1) i = 4;   // skip num_graphs scalar if present
    const float* W1  = (const float*)d_in[i + 0];
    const float* as1 = (const float*)d_in[i + 1];
    const float* ad1 = (const float*)d_in[i + 2];
    const float* b1  = (const float*)d_in[i + 3];
    const float* W2  = (const float*)d_in[i + 4];
    const float* as2 = (const float*)d_in[i + 5];
    const float* ad2 = (const float*)d_in[i + 6];
    const float* b2  = (const float*)d_in[i + 7];
    float* out = (float*)d_out;

    k_init<<<512, 256>>>();
    k_detect<<<16, 256>>>((const long long*)ei, (const long long*)batch);
    k_decodehist<<<2048, 256>>>(ei, batch);
    k_scan<<<1, 1024>>>();
    k_scatter<<<(N_EDGES_T + 255) / 256, 256>>>();
    k_gemm1<<<3125, 128>>>(x, W1, as1, ad1);
    k_agg1g2<<<6250, 256>>>(b1, W2, as2, ad2);
    k_agg2p<<<6250, 256>>>(b2);
    k_final<<<(NG * C2 + 255) / 256, 256>>>(out);
}

// round 6
// speedup vs baseline: 3.0241x; 1.3008x over previous
#include <cuda_runtime.h>
#include <cuda_fp16.h>
#include <cuda_bf16.h>

// Problem constants (fixed by setup_inputs)
#define N_NODES 50000
#define N_EDGES 1600000
#define N_EDGES_T (N_EDGES + N_NODES)   // with self loops = 1,650,000
#define F_IN 64
#define HC1 128          // H1*C1 = 4*32
#define C2 32
#define NG 512
#define NB 196           // ceil(N_NODES/256) scan blocks

// Scratch (device globals — no allocation allowed)
__device__ __half g_h1h[N_NODES * HC1];   // fp16 messages, layer 1
__device__ __half g_h2h[N_NODES * C2];    // fp16 messages, layer 2
__device__ float g_asrc1[N_NODES * 4];
__device__ float g_adst1[N_NODES * 4];
__device__ float g_asrc2[N_NODES];
__device__ float g_adst2[N_NODES];
__device__ float g_gsum[NG * C2];
__device__ float g_gcnt[NG];

// Decoded indices + CSR by dst
__device__ int g_src[N_EDGES];
__device__ int g_dst[N_EDGES];
__device__ int g_batch[N_NODES];
__device__ int g_deg[N_NODES];
__device__ int g_off[N_NODES + 1];
__device__ int g_pos[N_NODES];
__device__ int g_ssorted[N_EDGES_T];
__device__ int g_bsum[NB];
__device__ int g_bbase[NB];
__device__ int g_ei_not64;
__device__ int g_b_not64;

__device__ __forceinline__ float leaky(float v) {
    return v > 0.0f ? v : 0.2f * v;
}
__device__ __forceinline__ float eluf(float v) {
    return v > 0.0f ? v : (__expf(v) - 1.0f);
}

__global__ void k_init() {
    int i = blockIdx.x * blockDim.x + threadIdx.x;
    int stride = gridDim.x * blockDim.x;
    for (int j = i; j < N_NODES; j += stride) g_deg[j] = 1;   // self loop
    if (i < NG * C2) g_gsum[i] = 0.0f;
    if (i < NG)      g_gcnt[i] = 0.0f;
    if (i == 0) { g_ei_not64 = 0; g_b_not64 = 0; }
}

// Sampled dtype detection (see R5 notes: batch sampled at tail of safe range).
__global__ void k_detect(const long long* __restrict__ ei,
                         const long long* __restrict__ batch) {
    int i = blockIdx.x * blockDim.x + threadIdx.x;
    if (i < 4096) {
        long long v = ei[(long long)i * (N_EDGES / 4096)];
        if (v < 0 || v >= N_NODES) g_ei_not64 = 1;
    }
    if (i < 1000) {
        long long v = batch[N_NODES / 2 - 1 - i];
        if (v < 0 || v >= NG) g_b_not64 = 1;
    }
}

// Fused decode (int64|int32 -> int32) + dst histogram.
__global__ void k_decodehist(const void* __restrict__ ei, const void* __restrict__ batch) {
    int i = blockIdx.x * blockDim.x + threadIdx.x;
    int stride = gridDim.x * blockDim.x;
    bool e64 = (g_ei_not64 == 0);
    bool b64 = (g_b_not64 == 0);
    const long long* eL = (const long long*)ei;
    const int*       eI = (const int*)ei;
    const long long* bL = (const long long*)batch;
    const int*       bI = (const int*)batch;
    for (int j = i; j < N_EDGES; j += stride) {
        int s = e64 ? (int)eL[j]           : eI[j];
        int d = e64 ? (int)eL[N_EDGES + j] : eI[N_EDGES + j];
        g_src[j] = s;
        g_dst[j] = d;
        atomicAdd(&g_deg[d], 1);
    }
    for (int j = i; j < N_NODES; j += stride) {
        g_batch[j] = b64 ? (int)bL[j] : bI[j];
    }
}

// ---- Parallel exclusive prefix sum of degrees (3 phases) ----
__global__ void k_sum() {
    __shared__ int ws[8];
    int t = threadIdx.x;
    int idx = blockIdx.x * 256 + t;
    int v = (idx < N_NODES) ? g_deg[idx] : 0;
    #pragma unroll
    for (int o = 16; o > 0; o >>= 1) v += __shfl_xor_sync(0xffffffffu, v, o);
    if ((t & 31) == 0) ws[t >> 5] = v;
    __syncthreads();
    if (t < 8) {
        int s = ws[t];
        #pragma unroll
        for (int o = 4; o > 0; o >>= 1) s += __shfl_xor_sync(0xffu, s, o);
        if (t == 0) g_bsum[blockIdx.x] = s;
    }
}

__global__ void k_scanb() {
    __shared__ int ws[8];
    int t = threadIdx.x;        // 256 threads, NB=196 <= 256
    int v = (t < NB) ? g_bsum[t] : 0;
    int lane = t & 31, w = t >> 5;
    int incl = v;
    #pragma unroll
    for (int o = 1; o < 32; o <<= 1) {
        int n = __shfl_up_sync(0xffffffffu, incl, o);
        if (lane >= o) incl += n;
    }
    if (lane == 31) ws[w] = incl;
    __syncthreads();
    if (t < 8) {
        int s = ws[t];
        #pragma unroll
        for (int o = 1; o < 8; o <<= 1) {
            int n = __shfl_up_sync(0xffu, s, o);
            if (t >= o) s += n;
        }
        ws[t] = s;
    }
    __syncthreads();
    int base = (w > 0) ? ws[w - 1] : 0;
    incl += base;
    if (t < NB) g_bbase[t] = incl - v;   // exclusive base for block t
    if (t == NB - 1) g_off[N_NODES] = incl;
}

__global__ void k_fill() {
    __shared__ int ws[8];
    int t = threadIdx.x;
    int idx = blockIdx.x * 256 + t;
    int v = (idx < N_NODES) ? g_deg[idx] : 0;
    int lane = t & 31, w = t >> 5;
    int incl = v;
    #pragma unroll
    for (int o = 1; o < 32; o <<= 1) {
        int n = __shfl_up_sync(0xffffffffu, incl, o);
        if (lane >= o) incl += n;
    }
    if (lane == 31) ws[w] = incl;
    __syncthreads();
    if (t < 8) {
        int s = ws[t];
        #pragma unroll
        for (int o = 1; o < 8; o <<= 1) {
            int n = __shfl_up_sync(0xffu, s, o);
            if (t >= o) s += n;
        }
        ws[t] = s;
    }
    __syncthreads();
    int wbase = (w > 0) ? ws[w - 1] : 0;
    int off = g_bbase[blockIdx.x] + wbase + incl - v;
    if (idx < N_NODES) {
        g_off[idx] = off;
        g_pos[idx] = off;
    }
}

__global__ void k_scatter() {
    int e = blockIdx.x * blockDim.x + threadIdx.x;
    if (e >= N_EDGES_T) return;
    int s, d;
    if (e < N_EDGES) { s = g_src[e]; d = g_dst[e]; }
    else             { s = e - N_EDGES; d = s; }
    int p = atomicAdd(&g_pos[d], 1);
    g_ssorted[p] = s;
}

// GEMM1: h1 = x @ W1 (50000x64 @ 64x128), 16 rows/thread register blocking,
// fused per-head alpha epilogue (fp32), fp16 h1 store.
__global__ void k_gemm1(const float* __restrict__ x, const float* __restrict__ W1,
                        const float* __restrict__ a_src, const float* __restrict__ a_dst) {
    __shared__ float Ws[F_IN * HC1];   // 32 KB
    __shared__ float xs[F_IN][20];     // transposed x tile [k][row], padded
    int t = threadIdx.x;
    for (int i = t; i < F_IN * HC1; i += 128) Ws[i] = W1[i];
    float av_s = a_src[t];
    float av_d = a_dst[t];
    int head = t >> 5;
    int base = blockIdx.x * 16;
    {
        int k = t & 63;
        int r0 = t >> 6;
        #pragma unroll
        for (int j = 0; j < 8; ++j) {
            int r = r0 + j * 2;
            xs[k][r] = x[(base + r) * F_IN + k];
        }
    }
    __syncthreads();
    float acc[16];
    #pragma unroll
    for (int r = 0; r < 16; ++r) acc[r] = 0.0f;
    #pragma unroll
    for (int k = 0; k < F_IN; ++k) {
        float w = Ws[k * HC1 + t];
        float4 a = *(const float4*)&xs[k][0];
        float4 b = *(const float4*)&xs[k][4];
        float4 c = *(const float4*)&xs[k][8];
        float4 d = *(const float4*)&xs[k][12];
        acc[0]  += a.x * w; acc[1]  += a.y * w; acc[2]  += a.z * w; acc[3]  += a.w * w;
        acc[4]  += b.x * w; acc[5]  += b.y * w; acc[6]  += b.z * w; acc[7]  += b.w * w;
        acc[8]  += c.x * w; acc[9]  += c.y * w; acc[10] += c.z * w; acc[11] += c.w * w;
        acc[12] += d.x * w; acc[13] += d.y * w; acc[14] += d.z * w; acc[15] += d.w * w;
    }
    #pragma unroll
    for (int r = 0; r < 16; ++r) {
        int row = base + r;
        g_h1h[row * HC1 + t] = __float2half_rn(acc[r]);
        float vs = acc[r] * av_s, vd = acc[r] * av_d;
        #pragma unroll
        for (int o = 16; o > 0; o >>= 1) {
            vs += __shfl_xor_sync(0xffffffffu, vs, o);
            vd += __shfl_xor_sync(0xffffffffu, vd, o);
        }
        if ((t & 31) == 0) {
            g_asrc1[row * 4 + head] = vs;
            g_adst1[row * 4 + head] = vd;
        }
    }
}

// Fused layer-1 softmax+aggregate + ELU + GEMM2 + alpha2 epilogue.
// One warp per dst node; 8 warps/block; 6250 blocks * 8 = 50000 exactly.
__global__ void __launch_bounds__(256) k_agg1g2(
        const float* __restrict__ b1, const float* __restrict__ W2,
        const float* __restrict__ a_src2, const float* __restrict__ a_dst2) {
    __shared__ float W2s[HC1 * C2];    // 16 KB
    __shared__ float hs[8][HC1];       // 4 KB: per-warp ELU'd row
    int t = threadIdx.x;
    int w = t >> 5;
    int lane = t & 31;
    for (int i = t; i < HC1 * C2; i += 256) W2s[i] = W2[i];
    __syncthreads();

    int d = blockIdx.x * 8 + w;
    int h = lane >> 3;
    float adh = g_adst1[d * 4 + h];
    int beg = g_off[d], end = g_off[d + 1];
    float4 acc = make_float4(0.f, 0.f, 0.f, 0.f);
    float den = 0.0f;
    int j = beg;
    for (; j + 2 <= end; j += 2) {
        int s0 = g_ssorted[j];
        int s1 = g_ssorted[j + 1];
        float a0 = g_asrc1[s0 * 4 + h];
        float a1 = g_asrc1[s1 * 4 + h];
        uint2 q0 = *(const uint2*)(g_h1h + s0 * HC1 + lane * 4);
        uint2 q1 = *(const uint2*)(g_h1h + s1 * HC1 + lane * 4);
        float ex0 = __expf(leaky(a0 + adh));
        float ex1 = __expf(leaky(a1 + adh));
        float2 v00 = __half22float2(*reinterpret_cast<__half2*>(&q0.x));
        float2 v01 = __half22float2(*reinterpret_cast<__half2*>(&q0.y));
        float2 v10 = __half22float2(*reinterpret_cast<__half2*>(&q1.x));
        float2 v11 = __half22float2(*reinterpret_cast<__half2*>(&q1.y));
        acc.x += ex0 * v00.x + ex1 * v10.x;
        acc.y += ex0 * v00.y + ex1 * v10.y;
        acc.z += ex0 * v01.x + ex1 * v11.x;
        acc.w += ex0 * v01.y + ex1 * v11.y;
        den += ex0 + ex1;
    }
    if (j < end) {
        int s0 = g_ssorted[j];
        float a0 = g_asrc1[s0 * 4 + h];
        uint2 q0 = *(const uint2*)(g_h1h + s0 * HC1 + lane * 4);
        float ex0 = __expf(leaky(a0 + adh));
        float2 v00 = __half22float2(*reinterpret_cast<__half2*>(&q0.x));
        float2 v01 = __half22float2(*reinterpret_cast<__half2*>(&q0.y));
        acc.x += ex0 * v00.x;
        acc.y += ex0 * v00.y;
        acc.z += ex0 * v01.x;
        acc.w += ex0 * v01.y;
        den += ex0;
    }
    float inv = 1.0f / den;
    int c0 = lane * 4;
    hs[w][c0 + 0] = eluf(acc.x * inv + b1[c0 + 0]);
    hs[w][c0 + 1] = eluf(acc.y * inv + b1[c0 + 1]);
    hs[w][c0 + 2] = eluf(acc.z * inv + b1[c0 + 2]);
    hs[w][c0 + 3] = eluf(acc.w * inv + b1[c0 + 3]);
    __syncwarp();

    // GEMM2 row: h2 = hs[w] @ W2 (128 -> 32); lane = output channel.
    float acc2 = 0.0f;
    #pragma unroll
    for (int k = 0; k < HC1; k += 4) {
        float4 hv = *(const float4*)&hs[w][k];
        acc2 += hv.x * W2s[(k + 0) * C2 + lane];
        acc2 += hv.y * W2s[(k + 1) * C2 + lane];
        acc2 += hv.z * W2s[(k + 2) * C2 + lane];
        acc2 += hv.w * W2s[(k + 3) * C2 + lane];
    }
    g_h2h[d * C2 + lane] = __float2half_rn(acc2);
    float vs = acc2 * a_src2[lane];
    float vd = acc2 * a_dst2[lane];
    #pragma unroll
    for (int o = 16; o > 0; o >>= 1) {
        vs += __shfl_xor_sync(0xffffffffu, vs, o);
        vd += __shfl_xor_sync(0xffffffffu, vd, o);
    }
    if (lane == 0) {
        g_asrc2[d] = vs;
        g_adst2[d] = vd;
    }
}

// Fused layer-2 softmax+aggregate + bias + global mean pool accumulation.
__global__ void __launch_bounds__(256) k_agg2p(const float* __restrict__ b2) {
    int t = threadIdx.x;
    int w = t >> 5;
    int lane = t & 31;
    int d = blockIdx.x * 8 + w;
    float ad = g_adst2[d];
    int beg = g_off[d], end = g_off[d + 1];
    float acc = 0.0f, den = 0.0f;
    int j = beg;
    for (; j + 2 <= end; j += 2) {
        int s0 = g_ssorted[j];
        int s1 = g_ssorted[j + 1];
        float a0 = g_asrc2[s0];
        float a1 = g_asrc2[s1];
        float h0 = __half2float(g_h2h[s0 * C2 + lane]);
        float h1 = __half2float(g_h2h[s1 * C2 + lane]);
        float ex0 = __expf(leaky(a0 + ad));
        float ex1 = __expf(leaky(a1 + ad));
        acc += ex0 * h0 + ex1 * h1;
        den += ex0 + ex1;
    }
    if (j < end) {
        int s0 = g_ssorted[j];
        float ex0 = __expf(leaky(g_asrc2[s0] + ad));
        acc += ex0 * __half2float(g_h2h[s0 * C2 + lane]);
        den += ex0;
    }
    float outc = acc / den + b2[lane];
    int g = g_batch[d];
    atomicAdd(&g_gsum[g * C2 + lane], outc);
    if (lane == 0) atomicAdd(&g_gcnt[g], 1.0f);
}

__global__ void k_final(float* __restrict__ out) {
    int i = blockIdx.x * blockDim.x + threadIdx.x;
    if (i < NG * C2) out[i] = g_gsum[i] / fmaxf(g_gcnt[i >> 5], 1.0f);
}

extern "C" void kernel_launch(void* const* d_in, const int* in_sizes, int n_in,
                              void* d_out, int out_size) {
    const float* x     = (const float*)d_in[0];
    const void*  ei    = d_in[1];
    const void*  batch = d_in[2];
    int i = 3;
    if (n_in > 3 && in_sizes[3] == 1) i = 4;   // skip num_graphs scalar if present
    const float* W1  = (const float*)d_in[i + 0];
    const float* as1 = (const float*)d_in[i + 1];
    const float* ad1 = (const float*)d_in[i + 2];
    const float* b1  = (const float*)d_in[i + 3];
    const float* W2  = (const float*)d_in[i + 4];
    const float* as2 = (const float*)d_in[i + 5];
    const float* ad2 = (const float*)d_in[i + 6];
    const float* b2  = (const float*)d_in[i + 7];
    float* out = (float*)d_out;

    k_init<<<512, 256>>>();
    k_detect<<<16, 256>>>((const long long*)ei, (const long long*)batch);
    k_decodehist<<<2048, 256>>>(ei, batch);
    k_sum<<<NB, 256>>>();
    k_scanb<<<1, 256>>>();
    k_fill<<<NB, 256>>>();
    k_scatter<<<(N_EDGES_T + 255) / 256, 256>>>();
    k_gemm1<<<3125, 128>>>(x, W1, as1, ad1);
    k_agg1g2<<<6250, 256>>>(b1, W2, as2, ad2);
    k_agg2p<<<6250, 256>>>(b2);
    k_final<<<(NG * C2 + 255) / 256, 256>>>(out);
}

// round 7
// speedup vs baseline: 3.1318x; 1.0356x over previous
#include <cuda_runtime.h>
#include <cuda_fp16.h>
#include <cuda_bf16.h>

// Problem constants (fixed by setup_inputs)
#define N_NODES 50000
#define N_EDGES 1600000
#define N_EDGES_T (N_EDGES + N_NODES)   // with self loops = 1,650,000
#define F_IN 64
#define HC1 128          // H1*C1 = 4*32
#define C2 32
#define NG 512
#define NB 196           // ceil(N_NODES/256) scan blocks

// Scratch (device globals — no allocation allowed)
__device__ __half g_h1h[N_NODES * HC1];   // fp16 messages, layer 1
__device__ __half g_h2h[N_NODES * C2];    // fp16 messages, layer 2
__device__ float g_asrc1[N_NODES * 4];
__device__ float g_adst1[N_NODES * 4];
__device__ float g_asrc2[N_NODES];
__device__ float g_adst2[N_NODES];
__device__ float g_gsum[NG * C2];
__device__ float g_gcnt[NG];

// CSR by dst
__device__ int g_batch[N_NODES];
__device__ int g_deg[N_NODES];
__device__ int g_off[N_NODES + 1];
__device__ int g_pos[N_NODES];
__device__ int g_ssorted[N_EDGES_T];
__device__ int g_bsum[NB];
__device__ int g_bbase[NB];
__device__ int g_ei_not64;
__device__ int g_b_not64;

__device__ __forceinline__ float leaky(float v) {
    return v > 0.0f ? v : 0.2f * v;
}
__device__ __forceinline__ float eluf(float v) {
    return v > 0.0f ? v : (__expf(v) - 1.0f);
}

__global__ void k_init() {
    int i = blockIdx.x * blockDim.x + threadIdx.x;
    int stride = gridDim.x * blockDim.x;
    for (int j = i; j < N_NODES; j += stride) g_deg[j] = 1;   // self loop
    if (i < NG * C2) g_gsum[i] = 0.0f;
    if (i < NG)      g_gcnt[i] = 0.0f;
    if (i == 0) { g_ei_not64 = 0; g_b_not64 = 0; }
}

// Sampled dtype detection (batch sampled at tail of the safe half-range,
// where graph ids ~511 make packed-int32 data detectable).
__global__ void k_detect(const long long* __restrict__ ei,
                         const long long* __restrict__ batch) {
    int i = blockIdx.x * blockDim.x + threadIdx.x;
    if (i < 4096) {
        long long v = ei[(long long)i * (N_EDGES / 4096)];
        if (v < 0 || v >= N_NODES) g_ei_not64 = 1;
    }
    if (i < 1000) {
        long long v = batch[N_NODES / 2 - 1 - i];
        if (v < 0 || v >= NG) g_b_not64 = 1;
    }
}

// Histogram of dst (straight from ei) + batch decode.
__global__ void k_hist(const void* __restrict__ ei, const void* __restrict__ batch) {
    int i = blockIdx.x * blockDim.x + threadIdx.x;
    int stride = gridDim.x * blockDim.x;
    bool e64 = (g_ei_not64 == 0);
    bool b64 = (g_b_not64 == 0);
    const long long* eL = (const long long*)ei;
    const int*       eI = (const int*)ei;
    const long long* bL = (const long long*)batch;
    const int*       bI = (const int*)batch;
    for (int j = i; j < N_EDGES; j += stride) {
        int d = e64 ? (int)eL[N_EDGES + j] : eI[N_EDGES + j];
        atomicAdd(&g_deg[d], 1);
    }
    for (int j = i; j < N_NODES; j += stride) {
        g_batch[j] = b64 ? (int)bL[j] : bI[j];
    }
}

// ---- Parallel exclusive prefix sum of degrees (3 phases) ----
__global__ void k_sum() {
    __shared__ int ws[8];
    int t = threadIdx.x;
    int idx = blockIdx.x * 256 + t;
    int v = (idx < N_NODES) ? g_deg[idx] : 0;
    #pragma unroll
    for (int o = 16; o > 0; o >>= 1) v += __shfl_xor_sync(0xffffffffu, v, o);
    if ((t & 31) == 0) ws[t >> 5] = v;
    __syncthreads();
    if (t < 8) {
        int s = ws[t];
        #pragma unroll
        for (int o = 4; o > 0; o >>= 1) s += __shfl_xor_sync(0xffu, s, o);
        if (t == 0) g_bsum[blockIdx.x] = s;
    }
}

__global__ void k_scanb() {
    __shared__ int ws[8];
    int t = threadIdx.x;        // 256 threads, NB=196 <= 256
    int v = (t < NB) ? g_bsum[t] : 0;
    int lane = t & 31, w = t >> 5;
    int incl = v;
    #pragma unroll
    for (int o = 1; o < 32; o <<= 1) {
        int n = __shfl_up_sync(0xffffffffu, incl, o);
        if (lane >= o) incl += n;
    }
    if (lane == 31) ws[w] = incl;
    __syncthreads();
    if (t < 8) {
        int s = ws[t];
        #pragma unroll
        for (int o = 1; o < 8; o <<= 1) {
            int n = __shfl_up_sync(0xffu, s, o);
            if (t >= o) s += n;
        }
        ws[t] = s;
    }
    __syncthreads();
    int base = (w > 0) ? ws[w - 1] : 0;
    incl += base;
    if (t < NB) g_bbase[t] = incl - v;   // exclusive base for block t
    if (t == NB - 1) g_off[N_NODES] = incl;
}

__global__ void k_fill() {
    __shared__ int ws[8];
    int t = threadIdx.x;
    int idx = blockIdx.x * 256 + t;
    int v = (idx < N_NODES) ? g_deg[idx] : 0;
    int lane = t & 31, w = t >> 5;
    int incl = v;
    #pragma unroll
    for (int o = 1; o < 32; o <<= 1) {
        int n = __shfl_up_sync(0xffffffffu, incl, o);
        if (lane >= o) incl += n;
    }
    if (lane == 31) ws[w] = incl;
    __syncthreads();
    if (t < 8) {
        int s = ws[t];
        #pragma unroll
        for (int o = 1; o < 8; o <<= 1) {
            int n = __shfl_up_sync(0xffu, s, o);
            if (t >= o) s += n;
        }
        ws[t] = s;
    }
    __syncthreads();
    int wbase = (w > 0) ? ws[w - 1] : 0;
    int off = g_bbase[blockIdx.x] + wbase + incl - v;
    if (idx < N_NODES) {
        g_off[idx] = off;
        g_pos[idx] = off;
    }
}

// Scatter src ids into dst-sorted CSR order (reads ei directly).
__global__ void k_scatter(const void* __restrict__ ei) {
    int e = blockIdx.x * blockDim.x + threadIdx.x;
    if (e >= N_EDGES_T) return;
    bool e64 = (g_ei_not64 == 0);
    const long long* eL = (const long long*)ei;
    const int*       eI = (const int*)ei;
    int s, d;
    if (e < N_EDGES) {
        s = e64 ? (int)eL[e]           : eI[e];
        d = e64 ? (int)eL[N_EDGES + e] : eI[N_EDGES + e];
    } else {
        s = e - N_EDGES; d = s;
    }
    int p = atomicAdd(&g_pos[d], 1);
    g_ssorted[p] = s;
}

// GEMM1: h1 = x @ W1 (50000x64 @ 64x128), 16 rows/thread register blocking,
// fused per-head alpha epilogue (fp32), fp16 h1 store.
__global__ void k_gemm1(const float* __restrict__ x, const float* __restrict__ W1,
                        const float* __restrict__ a_src, const float* __restrict__ a_dst) {
    __shared__ float Ws[F_IN * HC1];   // 32 KB
    __shared__ float xs[F_IN][20];     // transposed x tile [k][row], padded
    int t = threadIdx.x;
    for (int i = t; i < F_IN * HC1; i += 128) Ws[i] = W1[i];
    float av_s = a_src[t];
    float av_d = a_dst[t];
    int head = t >> 5;
    int base = blockIdx.x * 16;
    {
        int k = t & 63;
        int r0 = t >> 6;
        #pragma unroll
        for (int j = 0; j < 8; ++j) {
            int r = r0 + j * 2;
            xs[k][r] = x[(base + r) * F_IN + k];
        }
    }
    __syncthreads();
    float acc[16];
    #pragma unroll
    for (int r = 0; r < 16; ++r) acc[r] = 0.0f;
    #pragma unroll
    for (int k = 0; k < F_IN; ++k) {
        float w = Ws[k * HC1 + t];
        float4 a = *(const float4*)&xs[k][0];
        float4 b = *(const float4*)&xs[k][4];
        float4 c = *(const float4*)&xs[k][8];
        float4 d = *(const float4*)&xs[k][12];
        acc[0]  += a.x * w; acc[1]  += a.y * w; acc[2]  += a.z * w; acc[3]  += a.w * w;
        acc[4]  += b.x * w; acc[5]  += b.y * w; acc[6]  += b.z * w; acc[7]  += b.w * w;
        acc[8]  += c.x * w; acc[9]  += c.y * w; acc[10] += c.z * w; acc[11] += c.w * w;
        acc[12] += d.x * w; acc[13] += d.y * w; acc[14] += d.z * w; acc[15] += d.w * w;
    }
    #pragma unroll
    for (int r = 0; r < 16; ++r) {
        int row = base + r;
        g_h1h[row * HC1 + t] = __float2half_rn(acc[r]);
        float vs = acc[r] * av_s, vd = acc[r] * av_d;
        #pragma unroll
        for (int o = 16; o > 0; o >>= 1) {
            vs += __shfl_xor_sync(0xffffffffu, vs, o);
            vd += __shfl_xor_sync(0xffffffffu, vd, o);
        }
        if ((t & 31) == 0) {
            g_asrc1[row * 4 + head] = vs;
            g_adst1[row * 4 + head] = vd;
        }
    }
}

// Fused layer-1 softmax+aggregate + ELU + GEMM2 + alpha2 epilogue.
// One warp per dst node; 8 warps/block; edge loop unrolled by 4.
__global__ void __launch_bounds__(256) k_agg1g2(
        const float* __restrict__ b1, const float* __restrict__ W2,
        const float* __restrict__ a_src2, const float* __restrict__ a_dst2) {
    __shared__ float W2s[HC1 * C2];    // 16 KB
    __shared__ float hs[8][HC1];       // 4 KB: per-warp ELU'd row
    int t = threadIdx.x;
    int w = t >> 5;
    int lane = t & 31;
    for (int i = t; i < HC1 * C2; i += 256) W2s[i] = W2[i];
    __syncthreads();

    int d = blockIdx.x * 8 + w;
    int h = lane >> 3;
    float adh = g_adst1[d * 4 + h];
    int beg = g_off[d], end = g_off[d + 1];
    float4 acc = make_float4(0.f, 0.f, 0.f, 0.f);
    float den = 0.0f;
    int j = beg;
    for (; j + 4 <= end; j += 4) {
        int s0 = g_ssorted[j];
        int s1 = g_ssorted[j + 1];
        int s2 = g_ssorted[j + 2];
        int s3 = g_ssorted[j + 3];
        float a0 = g_asrc1[s0 * 4 + h];
        float a1 = g_asrc1[s1 * 4 + h];
        float a2 = g_asrc1[s2 * 4 + h];
        float a3 = g_asrc1[s3 * 4 + h];
        uint2 q0 = *(const uint2*)(g_h1h + s0 * HC1 + lane * 4);
        uint2 q1 = *(const uint2*)(g_h1h + s1 * HC1 + lane * 4);
        uint2 q2 = *(const uint2*)(g_h1h + s2 * HC1 + lane * 4);
        uint2 q3 = *(const uint2*)(g_h1h + s3 * HC1 + lane * 4);
        float ex0 = __expf(leaky(a0 + adh));
        float ex1 = __expf(leaky(a1 + adh));
        float ex2 = __expf(leaky(a2 + adh));
        float ex3 = __expf(leaky(a3 + adh));
        float2 v00 = __half22float2(*reinterpret_cast<__half2*>(&q0.x));
        float2 v01 = __half22float2(*reinterpret_cast<__half2*>(&q0.y));
        float2 v10 = __half22float2(*reinterpret_cast<__half2*>(&q1.x));
        float2 v11 = __half22float2(*reinterpret_cast<__half2*>(&q1.y));
        float2 v20 = __half22float2(*reinterpret_cast<__half2*>(&q2.x));
        float2 v21 = __half22float2(*reinterpret_cast<__half2*>(&q2.y));
        float2 v30 = __half22float2(*reinterpret_cast<__half2*>(&q3.x));
        float2 v31 = __half22float2(*reinterpret_cast<__half2*>(&q3.y));
        acc.x += ex0 * v00.x + ex1 * v10.x + ex2 * v20.x + ex3 * v30.x;
        acc.y += ex0 * v00.y + ex1 * v10.y + ex2 * v20.y + ex3 * v30.y;
        acc.z += ex0 * v01.x + ex1 * v11.x + ex2 * v21.x + ex3 * v31.x;
        acc.w += ex0 * v01.y + ex1 * v11.y + ex2 * v21.y + ex3 * v31.y;
        den += (ex0 + ex1) + (ex2 + ex3);
    }
    for (; j < end; ++j) {
        int s0 = g_ssorted[j];
        float a0 = g_asrc1[s0 * 4 + h];
        uint2 q0 = *(const uint2*)(g_h1h + s0 * HC1 + lane * 4);
        float ex0 = __expf(leaky(a0 + adh));
        float2 v00 = __half22float2(*reinterpret_cast<__half2*>(&q0.x));
        float2 v01 = __half22float2(*reinterpret_cast<__half2*>(&q0.y));
        acc.x += ex0 * v00.x;
        acc.y += ex0 * v00.y;
        acc.z += ex0 * v01.x;
        acc.w += ex0 * v01.y;
        den += ex0;
    }
    float inv = 1.0f / den;
    int c0 = lane * 4;
    hs[w][c0 + 0] = eluf(acc.x * inv + b1[c0 + 0]);
    hs[w][c0 + 1] = eluf(acc.y * inv + b1[c0 + 1]);
    hs[w][c0 + 2] = eluf(acc.z * inv + b1[c0 + 2]);
    hs[w][c0 + 3] = eluf(acc.w * inv + b1[c0 + 3]);
    __syncwarp();

    // GEMM2 row: h2 = hs[w] @ W2 (128 -> 32); lane = output channel.
    float acc2 = 0.0f;
    #pragma unroll
    for (int k = 0; k < HC1; k += 4) {
        float4 hv = *(const float4*)&hs[w][k];
        acc2 += hv.x * W2s[(k + 0) * C2 + lane];
        acc2 += hv.y * W2s[(k + 1) * C2 + lane];
        acc2 += hv.z * W2s[(k + 2) * C2 + lane];
        acc2 += hv.w * W2s[(k + 3) * C2 + lane];
    }
    g_h2h[d * C2 + lane] = __float2half_rn(acc2);
    float vs = acc2 * a_src2[lane];
    float vd = acc2 * a_dst2[lane];
    #pragma unroll
    for (int o = 16; o > 0; o >>= 1) {
        vs += __shfl_xor_sync(0xffffffffu, vs, o);
        vd += __shfl_xor_sync(0xffffffffu, vd, o);
    }
    if (lane == 0) {
        g_asrc2[d] = vs;
        g_adst2[d] = vd;
    }
}

// Fused layer-2 softmax+aggregate + bias + global mean pool accumulation.
__global__ void __launch_bounds__(256) k_agg2p(const float* __restrict__ b2) {
    int t = threadIdx.x;
    int w = t >> 5;
    int lane = t & 31;
    int d = blockIdx.x * 8 + w;
    float ad = g_adst2[d];
    int beg = g_off[d], end = g_off[d + 1];
    float acc = 0.0f, den = 0.0f;
    int j = beg;
    for (; j + 4 <= end; j += 4) {
        int s0 = g_ssorted[j];
        int s1 = g_ssorted[j + 1];
        int s2 = g_ssorted[j + 2];
        int s3 = g_ssorted[j + 3];
        float a0 = g_asrc2[s0];
        float a1 = g_asrc2[s1];
        float a2 = g_asrc2[s2];
        float a3 = g_asrc2[s3];
        float h0 = __half2float(g_h2h[s0 * C2 + lane]);
        float h1 = __half2float(g_h2h[s1 * C2 + lane]);
        float h2 = __half2float(g_h2h[s2 * C2 + lane]);
        float h3 = __half2float(g_h2h[s3 * C2 + lane]);
        float ex0 = __expf(leaky(a0 + ad));
        float ex1 = __expf(leaky(a1 + ad));
        float ex2 = __expf(leaky(a2 + ad));
        float ex3 = __expf(leaky(a3 + ad));
        acc += ex0 * h0 + ex1 * h1 + ex2 * h2 + ex3 * h3;
        den += (ex0 + ex1) + (ex2 + ex3);
    }
    for (; j < end; ++j) {
        int s0 = g_ssorted[j];
        float ex0 = __expf(leaky(g_asrc2[s0] + ad));
        acc += ex0 * __half2float(g_h2h[s0 * C2 + lane]);
        den += ex0;
    }
    float outc = acc / den + b2[lane];
    int g = g_batch[d];
    atomicAdd(&g_gsum[g * C2 + lane], outc);
    if (lane == 0) atomicAdd(&g_gcnt[g], 1.0f);
}

__global__ void k_final(float* __restrict__ out) {
    int i = blockIdx.x * blockDim.x + threadIdx.x;
    if (i < NG * C2) out[i] = g_gsum[i] / fmaxf(g_gcnt[i >> 5], 1.0f);
}

extern "C" void kernel_launch(void* const* d_in, const int* in_sizes, int n_in,
                              void* d_out, int out_size) {
    const float* x     = (const float*)d_in[0];
    const void*  ei    = d_in[1];
    const void*  batch = d_in[2];
    int i = 3;
    if (n_in > 3 && in_sizes[3] == 1) i = 4;   // skip num_graphs scalar if present
    const float* W1  = (const float*)d_in[i + 0];
    const float* as1 = (const float*)d_in[i + 1];
    const float* ad1 = (const float*)d_in[i + 2];
    const float* b1  = (const float*)d_in[i + 3];
    const float* W2  = (const float*)d_in[i + 4];
    const float* as2 = (const float*)d_in[i + 5];
    const float* ad2 = (const float*)d_in[i + 6];
    const float* b2  = (const float*)d_in[i + 7];
    float* out = (float*)d_out;

    // Side stream for gemm1 overlap. Created once on the (uncaptured)
    // correctness call; capture records fork/join as graph dependencies.
    static cudaStream_t s_aux = nullptr;
    static cudaEvent_t ev_fork = nullptr, ev_join = nullptr;
    if (s_aux == nullptr) {
        cudaStreamCreate(&s_aux);
        cudaEventCreateWithFlags(&ev_fork, cudaEventDisableTiming);
        cudaEventCreateWithFlags(&ev_join, cudaEventDisableTiming);
    }

    // Fork: gemm1 depends only on x/W1 — run it alongside the CSR build.
    cudaEventRecord(ev_fork, 0);
    cudaStreamWaitEvent(s_aux, ev_fork, 0);
    k_gemm1<<<3125, 128, 0, s_aux>>>(x, W1, as1, ad1);
    cudaEventRecord(ev_join, s_aux);

    // CSR build chain on the main stream.
    k_init<<<512, 256>>>();
    k_detect<<<16, 256>>>((const long long*)ei, (const long long*)batch);
    k_hist<<<2048, 256>>>(ei, batch);
    k_sum<<<NB, 256>>>();
    k_scanb<<<1, 256>>>();
    k_fill<<<NB, 256>>>();
    k_scatter<<<(N_EDGES_T + 255) / 256, 256>>>(ei);

    // Join: aggregation needs both gemm1 results and the CSR.
    cudaStreamWaitEvent(0, ev_join, 0);
    k_agg1g2<<<6250, 256>>>(b1, W2, as2, ad2);
    k_agg2p<<<6250, 256>>>(b2);
    k_final<<<(NG * C2 + 255) / 256, 256>>>(out);
}